// round 6
// baseline (speedup 1.0000x reference)
#include <cuda_runtime.h>
#include <cuda_fp16.h>
#include <cstdint>

#define DEV __device__ __forceinline__

// ---------------- problem dims (fixed) ----------------
static constexpr int DIM_B   = 4096;
static constexpr int DIM_IN  = 1024;
static constexpr int DIM_H   = 16384;
static constexpr int DIM_OUT = 3072;

// ---------------- GEMM tiling ----------------
static constexpr int BM = 128, BN = 128, BK = 64, NST = 3;
static constexpr int LDT = 72;                         // padded row length (halves)
static constexpr int ABYTES = BM * LDT * 2;            // 18432
static constexpr int BBYTES = BN * LDT * 2;            // 18432
static constexpr int STAGEB = ABYTES + BBYTES;         // 36864
static constexpr int SB_OFF = NST * STAGEB;            // 110592
static constexpr int SMEM_BYTES = SB_OFF + 2 * BN * 4; // 111616

// ---------------- scratch (device globals; allocation-free) ----------------
__device__ __align__(128) __half g_Xh [(size_t)DIM_B * DIM_IN];
__device__ __align__(128) __half g_W1t[(size_t)DIM_H * DIM_IN];     // [DH, DIN]
__device__ __align__(128) __half g_W2t[(size_t)DIM_OUT * DIM_H];    // [DOUT, DH]
__device__ __align__(128) __half g_H  [(size_t)DIM_B * DIM_H];

// ---------------- PTX helpers (baseline ISA only: sm_80-class) ----------------
DEV uint32_t s2u(const void* p) { return (uint32_t)__cvta_generic_to_shared(p); }

DEV void cp16(uint32_t dst, const void* src) {
    asm volatile("cp.async.cg.shared.global [%0], [%1], 16;" :: "r"(dst), "l"(src));
}
DEV void cp_commit() { asm volatile("cp.async.commit_group;" ::: "memory"); }
DEV void cp_wait1()  { asm volatile("cp.async.wait_group 1;" ::: "memory"); }

DEV void ldsm4(uint32_t* r, uint32_t a) {
    asm volatile("ldmatrix.sync.aligned.m8n8.x4.shared.b16 {%0,%1,%2,%3}, [%4];"
                 : "=r"(r[0]), "=r"(r[1]), "=r"(r[2]), "=r"(r[3]) : "r"(a));
}

DEV void mma16816(float* c, const uint32_t* a, const uint32_t* b) {
    asm volatile(
        "mma.sync.aligned.m16n8k16.row.col.f32.f16.f16.f32 "
        "{%0,%1,%2,%3}, {%4,%5,%6,%7}, {%8,%9}, {%0,%1,%2,%3};"
        : "+f"(c[0]), "+f"(c[1]), "+f"(c[2]), "+f"(c[3])
        : "r"(a[0]), "r"(a[1]), "r"(a[2]), "r"(a[3]), "r"(b[0]), "r"(b[1]));
}

// scale arrives as a 4-byte scalar of unknown dtype (python int 1). Sniff bits.
DEV float load_scale(const float* p) {
    int iv = __float_as_int(*p);
    if (iv > -(1 << 24) && iv < (1 << 24)) return (float)iv;  // int bit pattern
    return __int_as_float(iv);                                 // real float bits
}

// ---------------- prepass: x -> fp16 ----------------
__global__ void cvt_x_kernel(const float* __restrict__ x, __half* __restrict__ o, int nquads) {
    int i = blockIdx.x * blockDim.x + threadIdx.x;
    if (i < nquads) {
        float4 v = *reinterpret_cast<const float4*>(x + (size_t)i * 4);
        reinterpret_cast<__half2*>(o)[2 * i + 0] = __floats2half2_rn(v.x, v.y);
        reinterpret_cast<__half2*>(o)[2 * i + 1] = __floats2half2_rn(v.z, v.w);
    }
}

// ---------------- prepass: ternarize + transpose ----------------
// W,NZ: [K,N] fp32 row-major.  Out[n,k] = tri(W[k,n] - sc*NZ[k,n]) fp16, shape [N,K]
__global__ void tern_t_kernel(const float* __restrict__ W, const float* __restrict__ NZ,
                              const float* __restrict__ scp, __half* __restrict__ Out,
                              int Kd, int Nd) {
    __shared__ __half t[32][33];
    float sc = load_scale(scp);
    int n0 = blockIdx.x * 32, k0 = blockIdx.y * 32;
    int tx = threadIdx.x, ty = threadIdx.y;  // 32 x 8
#pragma unroll
    for (int i = 0; i < 4; i++) {
        int k = ty + i * 8;
        size_t gi = (size_t)(k0 + k) * Nd + n0 + tx;
        float q = W[gi] - sc * NZ[gi];
        float v = (q > 1.0f) ? 1.0f : ((q < -1.0f) ? -1.0f : 0.0f);
        t[tx][k] = __float2half_rn(v);
    }
    __syncthreads();
#pragma unroll
    for (int i = 0; i < 4; i++) {
        int n = ty + i * 8;
        Out[(size_t)(n0 + n) * Kd + k0 + tx] = t[n][tx];
    }
}

// ---------------- GEMM stage loader ----------------
// A tile 128x64 + B tile 128x64, padded rows of 72 halves; 16B cp.async chunks.
DEV void load_stage(const __half* __restrict__ A, const __half* __restrict__ Bw,
                    int K, int m0, int n0, uint32_t base, int tid, int it) {
    int s  = it % NST;
    int k0 = it * BK;
    uint32_t sa = base + s * STAGEB;
    uint32_t sb = sa + ABYTES;
#pragma unroll
    for (int i = 0; i < 4; i++) {   // A: 1024 chunks / 256 threads
        int id = tid + i * 256;
        int r = id >> 3, c = (id & 7) * 8;
        cp16(sa + (uint32_t)(r * LDT + c) * 2,
             A + (size_t)(m0 + r) * K + k0 + c);
    }
#pragma unroll
    for (int i = 0; i < 4; i++) {   // B: 1024 chunks / 256 threads
        int id = tid + i * 256;
        int r = id >> 3, c = (id & 7) * 8;
        cp16(sb + (uint32_t)(r * LDT + c) * 2,
             Bw + (size_t)(n0 + r) * K + k0 + c);
    }
    cp_commit();
}

// ---------------- fused ternary GEMM ----------------
// C[m,n] = epi( sum_k A[m,k]*Bw[n,k] ),  A [M,K], Bw [N,K] fp16 K-major.
// TANH: C is half = tanh(s[n]*acc+b[n]);  else C is float = s[n]*acc+b[n].
template <bool TANH>
__global__ __launch_bounds__(256, 1) void gemm_tern(
    const __half* __restrict__ A, const __half* __restrict__ Bw,
    const float* __restrict__ sv, const float* __restrict__ bv,
    void* __restrict__ Cout, int Nld, int K) {

    extern __shared__ char smem[];
    uint32_t base = s2u(smem);

    int tid = threadIdx.x, wid = tid >> 5, lane = tid & 31;
    int m0 = blockIdx.y * BM, n0 = blockIdx.x * BN;
    int wm = (wid & 3) * 32;   // warp M offset
    int wn = (wid >> 2) * 64;  // warp N offset

    float* sS = reinterpret_cast<float*>(smem + SB_OFF);
    float* sB = sS + BN;
    for (int i = tid; i < BN; i += 256) { sS[i] = sv[n0 + i]; sB[i] = bv[n0 + i]; }

    // per-lane ldmatrix byte offsets within a stage (A at +0, B at +ABYTES)
    // A x4: matrices (k0|k8) for one m16 tile; lane: row = lane&15, kblk = lane>>4
    uint32_t aoff[2];
#pragma unroll
    for (int im = 0; im < 2; im++)
        aoff[im] = (uint32_t)((wm + im * 16 + (lane & 15)) * LDT + (lane >> 4) * 8) * 2;
    // B x4: two n8-tiles; g = lane>>3: ntile = g>>1, kblk = g&1, row = lane&7
    uint32_t boff[4];
    {
        int g = lane >> 3;
#pragma unroll
        for (int p = 0; p < 4; p++)
            boff[p] = (uint32_t)(ABYTES) +
                      (uint32_t)((wn + p * 16 + (g >> 1) * 8 + (lane & 7)) * LDT + (g & 1) * 8) * 2;
    }

    const int KT = K / BK;
    load_stage(A, Bw, K, m0, n0, base, tid, 0);
    load_stage(A, Bw, K, m0, n0, base, tid, 1);

    float acc[2][8][4];
#pragma unroll
    for (int im = 0; im < 2; im++)
#pragma unroll
        for (int in_ = 0; in_ < 8; in_++)
#pragma unroll
            for (int r = 0; r < 4; r++) acc[im][in_][r] = 0.0f;

    for (int it = 0; it < KT; ++it) {
        cp_wait1();            // stage `it` resident (<=1 group pending)
        __syncthreads();

        if (it + 2 < KT) load_stage(A, Bw, K, m0, n0, base, tid, it + 2);
        else cp_commit();      // keep group count aligned

        uint32_t sbase = base + (uint32_t)(it % NST) * STAGEB;
#pragma unroll
        for (int ks = 0; ks < 4; ks++) {
            uint32_t kb = (uint32_t)(ks * 16 * 2);
            uint32_t af[2][4], bf[8][2];
#pragma unroll
            for (int im = 0; im < 2; im++)
                ldsm4(af[im], sbase + aoff[im] + kb);
#pragma unroll
            for (int p = 0; p < 4; p++) {
                uint32_t r4[4];
                ldsm4(r4, sbase + boff[p] + kb);
                bf[2 * p][0] = r4[0]; bf[2 * p][1] = r4[1];
                bf[2 * p + 1][0] = r4[2]; bf[2 * p + 1][1] = r4[3];
            }
#pragma unroll
            for (int im = 0; im < 2; im++)
#pragma unroll
                for (int in_ = 0; in_ < 8; in_++)
                    mma16816(acc[im][in_], af[im], bf[in_]);
        }
        __syncthreads();       // all reads of this stage done before its slot refills
    }

    // -------- epilogue --------
    int row  = lane >> 2;        // 0..7
    int col2 = (lane & 3) * 2;   // 0,2,4,6
#pragma unroll
    for (int im = 0; im < 2; im++) {
        int mA = m0 + wm + im * 16 + row;
        int mB = mA + 8;
#pragma unroll
        for (int in_ = 0; in_ < 8; in_++) {
            int nl = wn + in_ * 8 + col2;   // local n within tile
            int n  = n0 + nl;
            float s0 = sS[nl], s1 = sS[nl + 1];
            float b0 = sB[nl], b1 = sB[nl + 1];
            float v0 = fmaf(s0, acc[im][in_][0], b0);
            float v1 = fmaf(s1, acc[im][in_][1], b1);
            float v2 = fmaf(s0, acc[im][in_][2], b0);
            float v3 = fmaf(s1, acc[im][in_][3], b1);
            if (TANH) {
                __half* C = reinterpret_cast<__half*>(Cout);
                *reinterpret_cast<__half2*>(C + (size_t)mA * Nld + n) =
                    __floats2half2_rn(tanhf(v0), tanhf(v1));
                *reinterpret_cast<__half2*>(C + (size_t)mB * Nld + n) =
                    __floats2half2_rn(tanhf(v2), tanhf(v3));
            } else {
                float* C = reinterpret_cast<float*>(Cout);
                *reinterpret_cast<float2*>(C + (size_t)mA * Nld + n) = make_float2(v0, v1);
                *reinterpret_cast<float2*>(C + (size_t)mB * Nld + n) = make_float2(v2, v3);
            }
        }
    }
}

extern "C" void kernel_launch(void* const* d_in, const int* in_sizes, int n_in,
                              void* d_out, int out_size) {
    const float* x  = (const float*)d_in[0];
    const float* w1 = (const float*)d_in[1];
    const float* s1 = (const float*)d_in[2];
    const float* b1 = (const float*)d_in[3];
    const float* w2 = (const float*)d_in[4];
    const float* s2 = (const float*)d_in[5];
    const float* b2 = (const float*)d_in[6];
    const float* n1 = (const float*)d_in[7];
    const float* n2 = (const float*)d_in[8];
    const float* sc = (const float*)d_in[9];
    (void)in_sizes; (void)n_in; (void)out_size;

    cudaFuncSetAttribute(gemm_tern<true>,  cudaFuncAttributeMaxDynamicSharedMemorySize, SMEM_BYTES);
    cudaFuncSetAttribute(gemm_tern<false>, cudaFuncAttributeMaxDynamicSharedMemorySize, SMEM_BYTES);

    __half *Xh, *W1t, *W2t, *H;
    cudaGetSymbolAddress((void**)&Xh,  g_Xh);
    cudaGetSymbolAddress((void**)&W1t, g_W1t);
    cudaGetSymbolAddress((void**)&W2t, g_W2t);
    cudaGetSymbolAddress((void**)&H,   g_H);

    int nquads = DIM_B * DIM_IN / 4;
    cvt_x_kernel<<<(nquads + 255) / 256, 256>>>(x, Xh, nquads);

    tern_t_kernel<<<dim3(DIM_H / 32, DIM_IN / 32), dim3(32, 8)>>>(w1, n1, sc, W1t, DIM_IN, DIM_H);
    tern_t_kernel<<<dim3(DIM_OUT / 32, DIM_H / 32), dim3(32, 8)>>>(w2, n2, sc, W2t, DIM_H, DIM_OUT);

    gemm_tern<true><<<dim3(DIM_H / BN, DIM_B / BM), 256, SMEM_BYTES>>>(
        Xh, W1t, s1, b1, (void*)H, DIM_H, DIM_IN);

    gemm_tern<false><<<dim3(DIM_OUT / BN, DIM_B / BM), 256, SMEM_BYTES>>>(
        H, W2t, s2, b2, d_out, DIM_OUT, DIM_H);
}

// round 7
// speedup vs baseline: 1.1897x; 1.1897x over previous
#include <cuda_runtime.h>
#include <cuda_fp16.h>
#include <cstdint>

#define DEV __device__ __forceinline__

// ---------------- problem dims (fixed) ----------------
static constexpr int DIM_B   = 4096;
static constexpr int DIM_IN  = 1024;
static constexpr int DIM_H   = 16384;
static constexpr int DIM_OUT = 3072;

// ---------------- GEMM tiling ----------------
static constexpr int BM = 256, BN = 128, BK = 64, NST = 3;
static constexpr int NTHR = 512;                       // 16 warps: 8 (M) x 2 (N)
static constexpr int LDT = 72;                         // padded row length (halves)
static constexpr int ABYTES = BM * LDT * 2;            // 36864
static constexpr int BBYTES = BN * LDT * 2;            // 18432
static constexpr int STAGEB = ABYTES + BBYTES;         // 55296
static constexpr int SB_OFF = NST * STAGEB;            // 165888
static constexpr int SMEM_BYTES = SB_OFF + 2 * BN * 4; // 166912

// ---------------- scratch (device globals; allocation-free) ----------------
__device__ __align__(128) __half g_Xh [(size_t)DIM_B * DIM_IN];
__device__ __align__(128) __half g_W1t[(size_t)DIM_H * DIM_IN];     // [DH, DIN]
__device__ __align__(128) __half g_W2t[(size_t)DIM_OUT * DIM_H];    // [DOUT, DH]
__device__ __align__(128) __half g_H  [(size_t)DIM_B * DIM_H];

// ---------------- PTX helpers (baseline ISA: sm_80-class only) ----------------
DEV uint32_t s2u(const void* p) { return (uint32_t)__cvta_generic_to_shared(p); }

DEV void cp16(uint32_t dst, const void* src) {
    asm volatile("cp.async.cg.shared.global [%0], [%1], 16;" :: "r"(dst), "l"(src));
}
DEV void cp_commit() { asm volatile("cp.async.commit_group;" ::: "memory"); }
DEV void cp_wait1()  { asm volatile("cp.async.wait_group 1;" ::: "memory"); }

DEV void ldsm4(uint32_t* r, uint32_t a) {
    asm volatile("ldmatrix.sync.aligned.m8n8.x4.shared.b16 {%0,%1,%2,%3}, [%4];"
                 : "=r"(r[0]), "=r"(r[1]), "=r"(r[2]), "=r"(r[3]) : "r"(a));
}

DEV void mma16816(float* c, const uint32_t* a, const uint32_t* b) {
    asm volatile(
        "mma.sync.aligned.m16n8k16.row.col.f32.f16.f16.f32 "
        "{%0,%1,%2,%3}, {%4,%5,%6,%7}, {%8,%9}, {%0,%1,%2,%3};"
        : "+f"(c[0]), "+f"(c[1]), "+f"(c[2]), "+f"(c[3])
        : "r"(a[0]), "r"(a[1]), "r"(a[2]), "r"(a[3]), "r"(b[0]), "r"(b[1]));
}

// scale arrives as a 4-byte scalar of unknown dtype (python int 1). Sniff bits.
DEV float load_scale(const float* p) {
    int iv = __float_as_int(*p);
    if (iv > -(1 << 24) && iv < (1 << 24)) return (float)iv;  // int bit pattern
    return __int_as_float(iv);                                 // real float bits
}

// ---------------- prepass: x -> fp16 ----------------
__global__ void cvt_x_kernel(const float* __restrict__ x, __half* __restrict__ o, int nquads) {
    int i = blockIdx.x * blockDim.x + threadIdx.x;
    if (i < nquads) {
        float4 v = *reinterpret_cast<const float4*>(x + (size_t)i * 4);
        reinterpret_cast<__half2*>(o)[2 * i + 0] = __floats2half2_rn(v.x, v.y);
        reinterpret_cast<__half2*>(o)[2 * i + 1] = __floats2half2_rn(v.z, v.w);
    }
}

// ---------------- prepass: ternarize + transpose ----------------
// W,NZ: [K,N] fp32 row-major.  Out[n,k] = tri(W[k,n] - sc*NZ[k,n]) fp16, shape [N,K]
__global__ void tern_t_kernel(const float* __restrict__ W, const float* __restrict__ NZ,
                              const float* __restrict__ scp, __half* __restrict__ Out,
                              int Kd, int Nd) {
    __shared__ __half t[32][33];
    float sc = load_scale(scp);
    int n0 = blockIdx.x * 32, k0 = blockIdx.y * 32;
    int tx = threadIdx.x, ty = threadIdx.y;  // 32 x 8
#pragma unroll
    for (int i = 0; i < 4; i++) {
        int k = ty + i * 8;
        size_t gi = (size_t)(k0 + k) * Nd + n0 + tx;
        float q = W[gi] - sc * NZ[gi];
        float v = (q > 1.0f) ? 1.0f : ((q < -1.0f) ? -1.0f : 0.0f);
        t[tx][k] = __float2half_rn(v);
    }
    __syncthreads();
#pragma unroll
    for (int i = 0; i < 4; i++) {
        int n = ty + i * 8;
        Out[(size_t)(n0 + n) * Kd + k0 + tx] = t[n][tx];
    }
}

// ---------------- GEMM stage loader ----------------
// A tile 256x64 + B tile 128x64, padded rows of 72 halves; 16B cp.async chunks.
DEV void load_stage(const __half* __restrict__ A, const __half* __restrict__ Bw,
                    int K, int m0, int n0, uint32_t base, int tid, int it) {
    int s  = it % NST;
    int k0 = it * BK;
    uint32_t sa = base + s * STAGEB;
    uint32_t sb = sa + ABYTES;
#pragma unroll
    for (int i = 0; i < 4; i++) {   // A: 2048 chunks / 512 threads
        int id = tid + i * NTHR;
        int r = id >> 3, c = (id & 7) * 8;
        cp16(sa + (uint32_t)(r * LDT + c) * 2,
             A + (size_t)(m0 + r) * K + k0 + c);
    }
#pragma unroll
    for (int i = 0; i < 2; i++) {   // B: 1024 chunks / 512 threads
        int id = tid + i * NTHR;
        int r = id >> 3, c = (id & 7) * 8;
        cp16(sb + (uint32_t)(r * LDT + c) * 2,
             Bw + (size_t)(n0 + r) * K + k0 + c);
    }
    cp_commit();
}

// ---------------- fused ternary GEMM ----------------
// C[m,n] = epi( sum_k A[m,k]*Bw[n,k] ),  A [M,K], Bw [N,K] fp16 K-major.
// TANH: C is half = tanh(s[n]*acc+b[n]);  else C is float = s[n]*acc+b[n].
template <bool TANH>
__global__ __launch_bounds__(NTHR, 1) void gemm_tern(
    const __half* __restrict__ A, const __half* __restrict__ Bw,
    const float* __restrict__ sv, const float* __restrict__ bv,
    void* __restrict__ Cout, int Nld, int K) {

    extern __shared__ char smem[];
    uint32_t base = s2u(smem);

    int tid = threadIdx.x, wid = tid >> 5, lane = tid & 31;
    int m0 = blockIdx.y * BM, n0 = blockIdx.x * BN;
    int wm = (wid & 7) * 32;   // warp M offset (8 warps along M)
    int wn = (wid >> 3) * 64;  // warp N offset (2 warps along N)

    float* sS = reinterpret_cast<float*>(smem + SB_OFF);
    float* sB = sS + BN;
    for (int i = tid; i < BN; i += NTHR) { sS[i] = sv[n0 + i]; sB[i] = bv[n0 + i]; }

    // per-lane ldmatrix byte offsets within a stage (A at +0, B at +ABYTES)
    uint32_t aoff[2];
#pragma unroll
    for (int im = 0; im < 2; im++)
        aoff[im] = (uint32_t)((wm + im * 16 + (lane & 15)) * LDT + (lane >> 4) * 8) * 2;
    uint32_t boff[4];
    {
        int g = lane >> 3;
#pragma unroll
        for (int p = 0; p < 4; p++)
            boff[p] = (uint32_t)(ABYTES) +
                      (uint32_t)((wn + p * 16 + (g >> 1) * 8 + (lane & 7)) * LDT + (g & 1) * 8) * 2;
    }

    const int KT = K / BK;
    load_stage(A, Bw, K, m0, n0, base, tid, 0);
    load_stage(A, Bw, K, m0, n0, base, tid, 1);

    float acc[2][8][4];
#pragma unroll
    for (int im = 0; im < 2; im++)
#pragma unroll
        for (int in_ = 0; in_ < 8; in_++)
#pragma unroll
            for (int r = 0; r < 4; r++) acc[im][in_][r] = 0.0f;

    for (int it = 0; it < KT; ++it) {
        cp_wait1();            // stage `it` resident (<=1 group pending)
        __syncthreads();       // writes by all threads visible; prior-iter reads done

        if (it + 2 < KT) load_stage(A, Bw, K, m0, n0, base, tid, it + 2);
        else cp_commit();      // keep group count aligned

        uint32_t sbase = base + (uint32_t)(it % NST) * STAGEB;
#pragma unroll
        for (int ks = 0; ks < 4; ks++) {
            uint32_t kb = (uint32_t)(ks * 16 * 2);
            uint32_t af[2][4], bf[8][2];
#pragma unroll
            for (int im = 0; im < 2; im++)
                ldsm4(af[im], sbase + aoff[im] + kb);
#pragma unroll
            for (int p = 0; p < 4; p++) {
                uint32_t r4[4];
                ldsm4(r4, sbase + boff[p] + kb);
                bf[2 * p][0] = r4[0]; bf[2 * p][1] = r4[1];
                bf[2 * p + 1][0] = r4[2]; bf[2 * p + 1][1] = r4[3];
            }
#pragma unroll
            for (int im = 0; im < 2; im++)
#pragma unroll
                for (int in_ = 0; in_ < 8; in_++)
                    mma16816(acc[im][in_], af[im], bf[in_]);
        }
        // NOTE: no second barrier needed — the slot written at iter it
        // ((it+2)%3) was last read at iter it-1, ordered by the top sync.
    }

    // -------- epilogue --------
    int row  = lane >> 2;        // 0..7
    int col2 = (lane & 3) * 2;   // 0,2,4,6
#pragma unroll
    for (int im = 0; im < 2; im++) {
        int mA = m0 + wm + im * 16 + row;
        int mB = mA + 8;
#pragma unroll
        for (int in_ = 0; in_ < 8; in_++) {
            int nl = wn + in_ * 8 + col2;   // local n within tile
            int n  = n0 + nl;
            float s0 = sS[nl], s1 = sS[nl + 1];
            float b0 = sB[nl], b1 = sB[nl + 1];
            float v0 = fmaf(s0, acc[im][in_][0], b0);
            float v1 = fmaf(s1, acc[im][in_][1], b1);
            float v2 = fmaf(s0, acc[im][in_][2], b0);
            float v3 = fmaf(s1, acc[im][in_][3], b1);
            if (TANH) {
                __half* C = reinterpret_cast<__half*>(Cout);
                *reinterpret_cast<__half2*>(C + (size_t)mA * Nld + n) =
                    __floats2half2_rn(tanhf(v0), tanhf(v1));
                *reinterpret_cast<__half2*>(C + (size_t)mB * Nld + n) =
                    __floats2half2_rn(tanhf(v2), tanhf(v3));
            } else {
                float* C = reinterpret_cast<float*>(Cout);
                *reinterpret_cast<float2*>(C + (size_t)mA * Nld + n) = make_float2(v0, v1);
                *reinterpret_cast<float2*>(C + (size_t)mB * Nld + n) = make_float2(v2, v3);
            }
        }
    }
}

extern "C" void kernel_launch(void* const* d_in, const int* in_sizes, int n_in,
                              void* d_out, int out_size) {
    const float* x  = (const float*)d_in[0];
    const float* w1 = (const float*)d_in[1];
    const float* s1 = (const float*)d_in[2];
    const float* b1 = (const float*)d_in[3];
    const float* w2 = (const float*)d_in[4];
    const float* s2 = (const float*)d_in[5];
    const float* b2 = (const float*)d_in[6];
    const float* n1 = (const float*)d_in[7];
    const float* n2 = (const float*)d_in[8];
    const float* sc = (const float*)d_in[9];
    (void)in_sizes; (void)n_in; (void)out_size;

    cudaFuncSetAttribute(gemm_tern<true>,  cudaFuncAttributeMaxDynamicSharedMemorySize, SMEM_BYTES);
    cudaFuncSetAttribute(gemm_tern<false>, cudaFuncAttributeMaxDynamicSharedMemorySize, SMEM_BYTES);

    __half *Xh, *W1t, *W2t, *H;
    cudaGetSymbolAddress((void**)&Xh,  g_Xh);
    cudaGetSymbolAddress((void**)&W1t, g_W1t);
    cudaGetSymbolAddress((void**)&W2t, g_W2t);
    cudaGetSymbolAddress((void**)&H,   g_H);

    int nquads = DIM_B * DIM_IN / 4;
    cvt_x_kernel<<<(nquads + 255) / 256, 256>>>(x, Xh, nquads);

    tern_t_kernel<<<dim3(DIM_H / 32, DIM_IN / 32), dim3(32, 8)>>>(w1, n1, sc, W1t, DIM_IN, DIM_H);
    tern_t_kernel<<<dim3(DIM_OUT / 32, DIM_H / 32), dim3(32, 8)>>>(w2, n2, sc, W2t, DIM_H, DIM_OUT);

    gemm_tern<true><<<dim3(DIM_H / BN, DIM_B / BM), NTHR, SMEM_BYTES>>>(
        Xh, W1t, s1, b1, (void*)H, DIM_H, DIM_IN);

    gemm_tern<false><<<dim3(DIM_OUT / BN, DIM_B / BM), NTHR, SMEM_BYTES>>>(
        H, W2t, s2, b2, d_out, DIM_OUT, DIM_H);
}

// round 8
// speedup vs baseline: 1.2129x; 1.0195x over previous
#include <cuda_runtime.h>
#include <cuda_fp16.h>
#include <cstdint>

#define DEV __device__ __forceinline__

// ---------------- problem dims (fixed) ----------------
static constexpr int DIM_B   = 4096;
static constexpr int DIM_IN  = 1024;
static constexpr int DIM_H   = 16384;
static constexpr int DIM_OUT = 3072;

// ---------------- GEMM tiling ----------------
static constexpr int BM = 256, BN = 128, BK = 64, NST = 3;
static constexpr int NTHR = 512;                       // 16 warps: 8 (M) x 2 (N)
static constexpr int LDT = 72;                         // padded row length (halves)
static constexpr int ABYTES = BM * LDT * 2;            // 36864
static constexpr int BBYTES = BN * LDT * 2;            // 18432
static constexpr int STAGEB = ABYTES + BBYTES;         // 55296
static constexpr int SB_OFF = NST * STAGEB;            // 165888
static constexpr int SMEM_BYTES = SB_OFF + 2 * BN * 4; // 166912

// ---------------- scratch (device globals; allocation-free) ----------------
__device__ __align__(128) __half g_Xh [(size_t)DIM_B * DIM_IN];
__device__ __align__(128) __half g_W1t[(size_t)DIM_H * DIM_IN];     // [DH, DIN]
__device__ __align__(128) __half g_W2t[(size_t)DIM_OUT * DIM_H];    // [DOUT, DH]
__device__ __align__(128) __half g_H  [(size_t)DIM_B * DIM_H];

// ---------------- PTX helpers (baseline ISA: sm_80-class only) ----------------
DEV uint32_t s2u(const void* p) { return (uint32_t)__cvta_generic_to_shared(p); }

DEV void cp16(uint32_t dst, const void* src) {
    asm volatile("cp.async.cg.shared.global [%0], [%1], 16;" :: "r"(dst), "l"(src));
}
DEV void cp_commit() { asm volatile("cp.async.commit_group;" ::: "memory"); }
DEV void cp_wait1()  { asm volatile("cp.async.wait_group 1;" ::: "memory"); }

DEV void ldsm4(uint32_t* r, uint32_t a) {
    asm volatile("ldmatrix.sync.aligned.m8n8.x4.shared.b16 {%0,%1,%2,%3}, [%4];"
                 : "=r"(r[0]), "=r"(r[1]), "=r"(r[2]), "=r"(r[3]) : "r"(a));
}

DEV void mma16816(float* c, const uint32_t* a, const uint32_t* b) {
    asm volatile(
        "mma.sync.aligned.m16n8k16.row.col.f32.f16.f16.f32 "
        "{%0,%1,%2,%3}, {%4,%5,%6,%7}, {%8,%9}, {%0,%1,%2,%3};"
        : "+f"(c[0]), "+f"(c[1]), "+f"(c[2]), "+f"(c[3])
        : "r"(a[0]), "r"(a[1]), "r"(a[2]), "r"(a[3]), "r"(b[0]), "r"(b[1]));
}

// scale arrives as a 4-byte scalar of unknown dtype (python int 1). Sniff bits.
DEV float load_scale(const float* p) {
    int iv = __float_as_int(*p);
    if (iv > -(1 << 24) && iv < (1 << 24)) return (float)iv;  // int bit pattern
    return __int_as_float(iv);                                 // real float bits
}

// ---------------- prepass: x -> fp16 ----------------
__global__ void cvt_x_kernel(const float* __restrict__ x, __half* __restrict__ o, int nquads) {
    int i = blockIdx.x * blockDim.x + threadIdx.x;
    if (i < nquads) {
        float4 v = *reinterpret_cast<const float4*>(x + (size_t)i * 4);
        reinterpret_cast<__half2*>(o)[2 * i + 0] = __floats2half2_rn(v.x, v.y);
        reinterpret_cast<__half2*>(o)[2 * i + 1] = __floats2half2_rn(v.z, v.w);
    }
}

// ---------------- prepass: ternarize + transpose ----------------
// W,NZ: [K,N] fp32 row-major.  Out[n,k] = tri(W[k,n] - sc*NZ[k,n]) fp16, shape [N,K]
__global__ void tern_t_kernel(const float* __restrict__ W, const float* __restrict__ NZ,
                              const float* __restrict__ scp, __half* __restrict__ Out,
                              int Kd, int Nd) {
    __shared__ __half t[32][33];
    float sc = load_scale(scp);
    int n0 = blockIdx.x * 32, k0 = blockIdx.y * 32;
    int tx = threadIdx.x, ty = threadIdx.y;  // 32 x 8
#pragma unroll
    for (int i = 0; i < 4; i++) {
        int k = ty + i * 8;
        size_t gi = (size_t)(k0 + k) * Nd + n0 + tx;
        float q = W[gi] - sc * NZ[gi];
        float v = (q > 1.0f) ? 1.0f : ((q < -1.0f) ? -1.0f : 0.0f);
        t[tx][k] = __float2half_rn(v);
    }
    __syncthreads();
#pragma unroll
    for (int i = 0; i < 4; i++) {
        int n = ty + i * 8;
        Out[(size_t)(n0 + n) * Kd + k0 + tx] = t[n][tx];
    }
}

// ---------------- GEMM stage loader ----------------
DEV void load_stage(const __half* __restrict__ A, const __half* __restrict__ Bw,
                    int K, int m0, int n0, uint32_t base, int tid, int it) {
    int s  = it % NST;
    int k0 = it * BK;
    uint32_t sa = base + s * STAGEB;
    uint32_t sb = sa + ABYTES;
#pragma unroll
    for (int i = 0; i < 4; i++) {   // A: 2048 chunks / 512 threads
        int id = tid + i * NTHR;
        int r = id >> 3, c = (id & 7) * 8;
        cp16(sa + (uint32_t)(r * LDT + c) * 2,
             A + (size_t)(m0 + r) * K + k0 + c);
    }
#pragma unroll
    for (int i = 0; i < 2; i++) {   // B: 1024 chunks / 512 threads
        int id = tid + i * NTHR;
        int r = id >> 3, c = (id & 7) * 8;
        cp16(sb + (uint32_t)(r * LDT + c) * 2,
             Bw + (size_t)(n0 + r) * K + k0 + c);
    }
    cp_commit();
}

// fragment fetch for one ks step (kb = ks*32 bytes)
DEV void ld_frags(uint32_t sbase, uint32_t kb, uint32_t aoff0, uint32_t boff0,
                  uint32_t af[2][4], uint32_t bf[8][2]) {
#pragma unroll
    for (int im = 0; im < 2; im++)
        ldsm4(af[im], sbase + aoff0 + (uint32_t)(im * 16 * LDT * 2) + kb);
#pragma unroll
    for (int p = 0; p < 4; p++) {
        uint32_t r4[4];
        ldsm4(r4, sbase + boff0 + (uint32_t)(p * 16 * LDT * 2) + kb);
        bf[2 * p][0] = r4[0]; bf[2 * p][1] = r4[1];
        bf[2 * p + 1][0] = r4[2]; bf[2 * p + 1][1] = r4[3];
    }
}

// ---------------- fused ternary GEMM ----------------
// C[m,n] = epi( sum_k A[m,k]*Bw[n,k] ),  A [M,K], Bw [N,K] fp16 K-major.
// TANH: C is half = tanh(s[n]*acc+b[n]);  else C is float = s[n]*acc+b[n].
template <bool TANH>
__global__ __launch_bounds__(NTHR, 1) void gemm_tern(
    const __half* __restrict__ A, const __half* __restrict__ Bw,
    const float* __restrict__ sv, const float* __restrict__ bv,
    void* __restrict__ Cout, int Nld, int K) {

    extern __shared__ char smem[];
    uint32_t base = s2u(smem);

    int tid = threadIdx.x, wid = tid >> 5, lane = tid & 31;
    int m0 = blockIdx.y * BM, n0 = blockIdx.x * BN;
    int wm = (wid & 7) * 32;   // warp M offset (8 warps along M)
    int wn = (wid >> 3) * 64;  // warp N offset (2 warps along N)

    float* sS = reinterpret_cast<float*>(smem + SB_OFF);
    float* sB = sS + BN;
    for (int i = tid; i < BN; i += NTHR) { sS[i] = sv[n0 + i]; sB[i] = bv[n0 + i]; }

    // base per-lane ldmatrix byte offsets within a stage (A at +0, B at +ABYTES)
    uint32_t aoff0 = (uint32_t)((wm + (lane & 15)) * LDT + (lane >> 4) * 8) * 2;
    uint32_t boff0;
    {
        int g = lane >> 3;
        boff0 = (uint32_t)ABYTES +
                (uint32_t)((wn + (g >> 1) * 8 + (lane & 7)) * LDT + (g & 1) * 8) * 2;
    }

    const int KT = K / BK;
    load_stage(A, Bw, K, m0, n0, base, tid, 0);
    load_stage(A, Bw, K, m0, n0, base, tid, 1);

    float acc[2][8][4];
#pragma unroll
    for (int im = 0; im < 2; im++)
#pragma unroll
        for (int in_ = 0; in_ < 8; in_++)
#pragma unroll
            for (int r = 0; r < 4; r++) acc[im][in_][r] = 0.0f;

    for (int it = 0; it < KT; ++it) {
        cp_wait1();            // stage `it` resident (<=1 group pending)
        __syncthreads();

        if (it + 2 < KT) load_stage(A, Bw, K, m0, n0, base, tid, it + 2);
        else cp_commit();      // keep group count aligned

        uint32_t sbase = base + (uint32_t)(it % NST) * STAGEB;

        // ---- ks-pipelined: prefetch frags for ks+1 before MMAs of ks ----
        uint32_t af[2][2][4], bf[2][8][2];
        ld_frags(sbase, 0, aoff0, boff0, af[0], bf[0]);
#pragma unroll
        for (int ks = 0; ks < 4; ks++) {
            int cur = ks & 1;
            if (ks < 3)
                ld_frags(sbase, (uint32_t)((ks + 1) * 32), aoff0, boff0,
                         af[cur ^ 1], bf[cur ^ 1]);
#pragma unroll
            for (int im = 0; im < 2; im++)
#pragma unroll
                for (int in_ = 0; in_ < 8; in_++)
                    mma16816(acc[im][in_], af[cur][im], bf[cur][in_]);
        }
        // slot written at iter it ((it+2)%3) was last read at iter it-1,
        // ordered by the top __syncthreads.
    }

    // -------- epilogue --------
    int row  = lane >> 2;        // 0..7
    int col2 = (lane & 3) * 2;   // 0,2,4,6
#pragma unroll
    for (int im = 0; im < 2; im++) {
        int mA = m0 + wm + im * 16 + row;
        int mB = mA + 8;
#pragma unroll
        for (int in_ = 0; in_ < 8; in_++) {
            int nl = wn + in_ * 8 + col2;   // local n within tile
            int n  = n0 + nl;
            float s0 = sS[nl], s1 = sS[nl + 1];
            float b0 = sB[nl], b1 = sB[nl + 1];
            float v0 = fmaf(s0, acc[im][in_][0], b0);
            float v1 = fmaf(s1, acc[im][in_][1], b1);
            float v2 = fmaf(s0, acc[im][in_][2], b0);
            float v3 = fmaf(s1, acc[im][in_][3], b1);
            if (TANH) {
                __half* C = reinterpret_cast<__half*>(Cout);
                *reinterpret_cast<__half2*>(C + (size_t)mA * Nld + n) =
                    __floats2half2_rn(tanhf(v0), tanhf(v1));
                *reinterpret_cast<__half2*>(C + (size_t)mB * Nld + n) =
                    __floats2half2_rn(tanhf(v2), tanhf(v3));
            } else {
                float* C = reinterpret_cast<float*>(Cout);
                *reinterpret_cast<float2*>(C + (size_t)mA * Nld + n) = make_float2(v0, v1);
                *reinterpret_cast<float2*>(C + (size_t)mB * Nld + n) = make_float2(v2, v3);
            }
        }
    }
}

extern "C" void kernel_launch(void* const* d_in, const int* in_sizes, int n_in,
                              void* d_out, int out_size) {
    const float* x  = (const float*)d_in[0];
    const float* w1 = (const float*)d_in[1];
    const float* s1 = (const float*)d_in[2];
    const float* b1 = (const float*)d_in[3];
    const float* w2 = (const float*)d_in[4];
    const float* s2 = (const float*)d_in[5];
    const float* b2 = (const float*)d_in[6];
    const float* n1 = (const float*)d_in[7];
    const float* n2 = (const float*)d_in[8];
    const float* sc = (const float*)d_in[9];
    (void)in_sizes; (void)n_in; (void)out_size;

    cudaFuncSetAttribute(gemm_tern<true>,  cudaFuncAttributeMaxDynamicSharedMemorySize, SMEM_BYTES);
    cudaFuncSetAttribute(gemm_tern<false>, cudaFuncAttributeMaxDynamicSharedMemorySize, SMEM_BYTES);

    __half *Xh, *W1t, *W2t, *H;
    cudaGetSymbolAddress((void**)&Xh,  g_Xh);
    cudaGetSymbolAddress((void**)&W1t, g_W1t);
    cudaGetSymbolAddress((void**)&W2t, g_W2t);
    cudaGetSymbolAddress((void**)&H,   g_H);

    int nquads = DIM_B * DIM_IN / 4;
    cvt_x_kernel<<<(nquads + 255) / 256, 256>>>(x, Xh, nquads);

    tern_t_kernel<<<dim3(DIM_H / 32, DIM_IN / 32), dim3(32, 8)>>>(w1, n1, sc, W1t, DIM_IN, DIM_H);
    tern_t_kernel<<<dim3(DIM_OUT / 32, DIM_H / 32), dim3(32, 8)>>>(w2, n2, sc, W2t, DIM_H, DIM_OUT);

    gemm_tern<true><<<dim3(DIM_H / BN, DIM_B / BM), NTHR, SMEM_BYTES>>>(
        Xh, W1t, s1, b1, (void*)H, DIM_H, DIM_IN);

    gemm_tern<false><<<dim3(DIM_OUT / BN, DIM_B / BM), NTHR, SMEM_BYTES>>>(
        H, W2t, s2, b2, d_out, DIM_OUT, DIM_H);
}

// round 9
// speedup vs baseline: 1.2679x; 1.0454x over previous
#include <cuda_runtime.h>
#include <cuda_fp16.h>
#include <cstdint>

#define DEV __device__ __forceinline__

// ---------------- problem dims (fixed) ----------------
static constexpr int DIM_B   = 4096;
static constexpr int DIM_IN  = 1024;
static constexpr int DIM_H   = 16384;
static constexpr int DIM_OUT = 3072;

// ---------------- GEMM tiling ----------------
// 2 CTAs/SM: 256 thr, <=128 regs (launch_bounds), 111.6 KB smem per CTA.
static constexpr int BM = 128, BN = 128, BK = 64, NST = 3;
static constexpr int NTHR = 256;                       // 8 warps: 4 (M) x 2 (N)
static constexpr int LDT = 72;                         // padded row length (halves)
static constexpr int ABYTES = BM * LDT * 2;            // 18432
static constexpr int BBYTES = BN * LDT * 2;            // 18432
static constexpr int STAGEB = ABYTES + BBYTES;         // 36864
static constexpr int SB_OFF = NST * STAGEB;            // 110592
static constexpr int SMEM_BYTES = SB_OFF + 2 * BN * 4; // 111616

// ---------------- scratch (device globals; allocation-free) ----------------
__device__ __align__(128) __half g_Xh [(size_t)DIM_B * DIM_IN];
__device__ __align__(128) __half g_W1t[(size_t)DIM_H * DIM_IN];     // [DH, DIN]
__device__ __align__(128) __half g_W2t[(size_t)DIM_OUT * DIM_H];    // [DOUT, DH]
__device__ __align__(128) __half g_H  [(size_t)DIM_B * DIM_H];

// ---------------- PTX helpers (baseline ISA: sm_80-class only) ----------------
DEV uint32_t s2u(const void* p) { return (uint32_t)__cvta_generic_to_shared(p); }

DEV void cp16(uint32_t dst, const void* src) {
    asm volatile("cp.async.cg.shared.global [%0], [%1], 16;" :: "r"(dst), "l"(src));
}
DEV void cp_commit() { asm volatile("cp.async.commit_group;" ::: "memory"); }
DEV void cp_wait1()  { asm volatile("cp.async.wait_group 1;" ::: "memory"); }

DEV void ldsm4(uint32_t* r, uint32_t a) {
    asm volatile("ldmatrix.sync.aligned.m8n8.x4.shared.b16 {%0,%1,%2,%3}, [%4];"
                 : "=r"(r[0]), "=r"(r[1]), "=r"(r[2]), "=r"(r[3]) : "r"(a));
}

DEV void mma16816(float* c, const uint32_t* a, const uint32_t* b) {
    asm volatile(
        "mma.sync.aligned.m16n8k16.row.col.f32.f16.f16.f32 "
        "{%0,%1,%2,%3}, {%4,%5,%6,%7}, {%8,%9}, {%0,%1,%2,%3};"
        : "+f"(c[0]), "+f"(c[1]), "+f"(c[2]), "+f"(c[3])
        : "r"(a[0]), "r"(a[1]), "r"(a[2]), "r"(a[3]), "r"(b[0]), "r"(b[1]));
}

// scale arrives as a 4-byte scalar of unknown dtype (python int 1). Sniff bits.
DEV float load_scale(const float* p) {
    int iv = __float_as_int(*p);
    if (iv > -(1 << 24) && iv < (1 << 24)) return (float)iv;  // int bit pattern
    return __int_as_float(iv);                                 // real float bits
}

// ---------------- prepass: x -> fp16 ----------------
__global__ void cvt_x_kernel(const float* __restrict__ x, __half* __restrict__ o, int nquads) {
    int i = blockIdx.x * blockDim.x + threadIdx.x;
    if (i < nquads) {
        float4 v = *reinterpret_cast<const float4*>(x + (size_t)i * 4);
        reinterpret_cast<__half2*>(o)[2 * i + 0] = __floats2half2_rn(v.x, v.y);
        reinterpret_cast<__half2*>(o)[2 * i + 1] = __floats2half2_rn(v.z, v.w);
    }
}

// ---------------- prepass: ternarize + transpose ----------------
// W,NZ: [K,N] fp32 row-major.  Out[n,k] = tri(W[k,n] - sc*NZ[k,n]) fp16, shape [N,K]
__global__ void tern_t_kernel(const float* __restrict__ W, const float* __restrict__ NZ,
                              const float* __restrict__ scp, __half* __restrict__ Out,
                              int Kd, int Nd) {
    __shared__ __half t[32][33];
    float sc = load_scale(scp);
    int n0 = blockIdx.x * 32, k0 = blockIdx.y * 32;
    int tx = threadIdx.x, ty = threadIdx.y;  // 32 x 8
#pragma unroll
    for (int i = 0; i < 4; i++) {
        int k = ty + i * 8;
        size_t gi = (size_t)(k0 + k) * Nd + n0 + tx;
        float q = W[gi] - sc * NZ[gi];
        float v = (q > 1.0f) ? 1.0f : ((q < -1.0f) ? -1.0f : 0.0f);
        t[tx][k] = __float2half_rn(v);
    }
    __syncthreads();
#pragma unroll
    for (int i = 0; i < 4; i++) {
        int n = ty + i * 8;
        Out[(size_t)(n0 + n) * Kd + k0 + tx] = t[n][tx];
    }
}

// ---------------- GEMM stage loader ----------------
// A tile 128x64 + B tile 128x64, padded rows of 72 halves; 16B cp.async chunks.
DEV void load_stage(const __half* __restrict__ A, const __half* __restrict__ Bw,
                    int K, int m0, int n0, uint32_t base, int tid, int it) {
    int s  = it % NST;
    int k0 = it * BK;
    uint32_t sa = base + s * STAGEB;
    uint32_t sb = sa + ABYTES;
#pragma unroll
    for (int i = 0; i < 4; i++) {   // A: 1024 chunks / 256 threads
        int id = tid + i * NTHR;
        int r = id >> 3, c = (id & 7) * 8;
        cp16(sa + (uint32_t)(r * LDT + c) * 2,
             A + (size_t)(m0 + r) * K + k0 + c);
    }
#pragma unroll
    for (int i = 0; i < 4; i++) {   // B: 1024 chunks / 256 threads
        int id = tid + i * NTHR;
        int r = id >> 3, c = (id & 7) * 8;
        cp16(sb + (uint32_t)(r * LDT + c) * 2,
             Bw + (size_t)(n0 + r) * K + k0 + c);
    }
    cp_commit();
}

// ---------------- fused ternary GEMM ----------------
// C[m,n] = epi( sum_k A[m,k]*Bw[n,k] ),  A [M,K], Bw [N,K] fp16 K-major.
// TANH: C is half = tanh(s[n]*acc+b[n]);  else C is float = s[n]*acc+b[n].
template <bool TANH>
__global__ __launch_bounds__(NTHR, 2) void gemm_tern(
    const __half* __restrict__ A, const __half* __restrict__ Bw,
    const float* __restrict__ sv, const float* __restrict__ bv,
    void* __restrict__ Cout, int Nld, int K) {

    extern __shared__ char smem[];
    uint32_t base = s2u(smem);

    int tid = threadIdx.x, wid = tid >> 5, lane = tid & 31;
    int m0 = blockIdx.y * BM, n0 = blockIdx.x * BN;
    int wm = (wid & 3) * 32;   // warp M offset (4 warps along M)
    int wn = (wid >> 2) * 64;  // warp N offset (2 warps along N)

    float* sS = reinterpret_cast<float*>(smem + SB_OFF);
    float* sB = sS + BN;
    for (int i = tid; i < BN; i += NTHR) { sS[i] = sv[n0 + i]; sB[i] = bv[n0 + i]; }

    // per-lane ldmatrix byte offsets within a stage (A at +0, B at +ABYTES)
    uint32_t aoff[2];
#pragma unroll
    for (int im = 0; im < 2; im++)
        aoff[im] = (uint32_t)((wm + im * 16 + (lane & 15)) * LDT + (lane >> 4) * 8) * 2;
    uint32_t boff[4];
    {
        int g = lane >> 3;
#pragma unroll
        for (int p = 0; p < 4; p++)
            boff[p] = (uint32_t)(ABYTES) +
                      (uint32_t)((wn + p * 16 + (g >> 1) * 8 + (lane & 7)) * LDT + (g & 1) * 8) * 2;
    }

    const int KT = K / BK;
    load_stage(A, Bw, K, m0, n0, base, tid, 0);
    load_stage(A, Bw, K, m0, n0, base, tid, 1);

    float acc[2][8][4];
#pragma unroll
    for (int im = 0; im < 2; im++)
#pragma unroll
        for (int in_ = 0; in_ < 8; in_++)
#pragma unroll
            for (int r = 0; r < 4; r++) acc[im][in_][r] = 0.0f;

    for (int it = 0; it < KT; ++it) {
        cp_wait1();            // stage `it` resident (<=1 group pending)
        __syncthreads();       // writes visible; prior-iter reads complete

        if (it + 2 < KT) load_stage(A, Bw, K, m0, n0, base, tid, it + 2);
        else cp_commit();      // keep group count aligned

        uint32_t sbase = base + (uint32_t)(it % NST) * STAGEB;
#pragma unroll
        for (int ks = 0; ks < 4; ks++) {
            uint32_t kb = (uint32_t)(ks * 16 * 2);
            uint32_t af[2][4], bf[8][2];
#pragma unroll
            for (int im = 0; im < 2; im++)
                ldsm4(af[im], sbase + aoff[im] + kb);
#pragma unroll
            for (int p = 0; p < 4; p++) {
                uint32_t r4[4];
                ldsm4(r4, sbase + boff[p] + kb);
                bf[2 * p][0] = r4[0]; bf[2 * p][1] = r4[1];
                bf[2 * p + 1][0] = r4[2]; bf[2 * p + 1][1] = r4[3];
            }
#pragma unroll
            for (int im = 0; im < 2; im++)
#pragma unroll
                for (int in_ = 0; in_ < 8; in_++)
                    mma16816(acc[im][in_], af[im], bf[in_]);
        }
        // slot written at iter it ((it+2)%3) was last read at iter it-1,
        // ordered by the top __syncthreads.
    }

    // -------- epilogue --------
    int row  = lane >> 2;        // 0..7
    int col2 = (lane & 3) * 2;   // 0,2,4,6
#pragma unroll
    for (int im = 0; im < 2; im++) {
        int mA = m0 + wm + im * 16 + row;
        int mB = mA + 8;
#pragma unroll
        for (int in_ = 0; in_ < 8; in_++) {
            int nl = wn + in_ * 8 + col2;   // local n within tile
            int n  = n0 + nl;
            float s0 = sS[nl], s1 = sS[nl + 1];
            float b0 = sB[nl], b1 = sB[nl + 1];
            float v0 = fmaf(s0, acc[im][in_][0], b0);
            float v1 = fmaf(s1, acc[im][in_][1], b1);
            float v2 = fmaf(s0, acc[im][in_][2], b0);
            float v3 = fmaf(s1, acc[im][in_][3], b1);
            if (TANH) {
                __half* C = reinterpret_cast<__half*>(Cout);
                *reinterpret_cast<__half2*>(C + (size_t)mA * Nld + n) =
                    __floats2half2_rn(tanhf(v0), tanhf(v1));
                *reinterpret_cast<__half2*>(C + (size_t)mB * Nld + n) =
                    __floats2half2_rn(tanhf(v2), tanhf(v3));
            } else {
                float* C = reinterpret_cast<float*>(Cout);
                *reinterpret_cast<float2*>(C + (size_t)mA * Nld + n) = make_float2(v0, v1);
                *reinterpret_cast<float2*>(C + (size_t)mB * Nld + n) = make_float2(v2, v3);
            }
        }
    }
}

extern "C" void kernel_launch(void* const* d_in, const int* in_sizes, int n_in,
                              void* d_out, int out_size) {
    const float* x  = (const float*)d_in[0];
    const float* w1 = (const float*)d_in[1];
    const float* s1 = (const float*)d_in[2];
    const float* b1 = (const float*)d_in[3];
    const float* w2 = (const float*)d_in[4];
    const float* s2 = (const float*)d_in[5];
    const float* b2 = (const float*)d_in[6];
    const float* n1 = (const float*)d_in[7];
    const float* n2 = (const float*)d_in[8];
    const float* sc = (const float*)d_in[9];
    (void)in_sizes; (void)n_in; (void)out_size;

    cudaFuncSetAttribute(gemm_tern<true>,  cudaFuncAttributeMaxDynamicSharedMemorySize, SMEM_BYTES);
    cudaFuncSetAttribute(gemm_tern<false>, cudaFuncAttributeMaxDynamicSharedMemorySize, SMEM_BYTES);

    __half *Xh, *W1t, *W2t, *H;
    cudaGetSymbolAddress((void**)&Xh,  g_Xh);
    cudaGetSymbolAddress((void**)&W1t, g_W1t);
    cudaGetSymbolAddress((void**)&W2t, g_W2t);
    cudaGetSymbolAddress((void**)&H,   g_H);

    int nquads = DIM_B * DIM_IN / 4;
    cvt_x_kernel<<<(nquads + 255) / 256, 256>>>(x, Xh, nquads);

    tern_t_kernel<<<dim3(DIM_H / 32, DIM_IN / 32), dim3(32, 8)>>>(w1, n1, sc, W1t, DIM_IN, DIM_H);
    tern_t_kernel<<<dim3(DIM_OUT / 32, DIM_H / 32), dim3(32, 8)>>>(w2, n2, sc, W2t, DIM_H, DIM_OUT);

    gemm_tern<true><<<dim3(DIM_H / BN, DIM_B / BM), NTHR, SMEM_BYTES>>>(
        Xh, W1t, s1, b1, (void*)H, DIM_H, DIM_IN);

    gemm_tern<false><<<dim3(DIM_OUT / BN, DIM_B / BM), NTHR, SMEM_BYTES>>>(
        H, W2t, s2, b2, d_out, DIM_OUT, DIM_H);
}